// round 1
// baseline (speedup 1.0000x reference)
#include <cuda_runtime.h>
#include <math.h>

#define WSZ 7
#define NTOK 49
#define CDIM 384
#define NHEAD 12
#define KDIM 32
#define BDIM 64
#define HDIM 28
#define LDIM 784
#define HIDD 1536
#define NWIN 1024
#define MROWS 50176
#define QKVO 1152

// ---------------- scratch (device globals; allocation-free) ----------------
__device__ float g_xn[(size_t)MROWS * CDIM];     // LN output (windowed, then reused for LN_m)
__device__ float g_qkv[(size_t)MROWS * QKVO];    // [win, head, tok, 96]
__device__ float g_o[(size_t)MROWS * CDIM];      // attention output (window order)
__device__ float g_x1[(size_t)MROWS * CDIM];     // x after attn residual (B,L,C order)
__device__ float g_x2[(size_t)MROWS * CDIM];     // x after conv+BN (B,L,C order)
__device__ float g_hmid[(size_t)MROWS * HIDD];   // MLP hidden

// window-row -> (b*L + l) row of the (B,L,C) tensor
__device__ __forceinline__ int win_row_to_xl(int r) {
    int win = r / NTOK, n = r % NTOK;
    int b = win >> 4;
    int wh = (win >> 2) & 3, ww = win & 3;
    int ih = n / WSZ, iw = n % WSZ;
    int h = wh * WSZ + ih, w = ww * WSZ + iw;
    return b * LDIM + h * HDIM + w;
}

// ---------------- LayerNorm: one warp per row ----------------
template<bool WINDOWED>
__global__ void __launch_bounds__(256)
ln_kernel(const float* __restrict__ x, const float* __restrict__ g,
          const float* __restrict__ bvec, float* __restrict__ out)
{
    int r = blockIdx.x * 8 + (threadIdx.x >> 5);
    int lane = threadIdx.x & 31;
    if (r >= MROWS) return;
    int src_row = WINDOWED ? win_row_to_xl(r) : r;
    const float* src = x + (size_t)src_row * CDIM;
    float vals[12];
    float s = 0.f, s2 = 0.f;
#pragma unroll
    for (int i = 0; i < 12; i++) {
        float v = src[lane + 32 * i];
        vals[i] = v;
        s += v;
        s2 = fmaf(v, v, s2);
    }
#pragma unroll
    for (int o = 16; o; o >>= 1) {
        s  += __shfl_xor_sync(0xffffffffu, s,  o);
        s2 += __shfl_xor_sync(0xffffffffu, s2, o);
    }
    float mean = s * (1.f / CDIM);
    float var  = s2 * (1.f / CDIM) - mean * mean;
    float inv  = rsqrtf(var + 1e-5f);
    float* dst = out + (size_t)r * CDIM;
#pragma unroll
    for (int i = 0; i < 12; i++) {
        int c = lane + 32 * i;
        dst[c] = (vals[i] - mean) * inv * g[c] + bvec[c];
    }
}

// ---------------- generic tiled fp32 GEMM: out = A(MxK) * W(NxK)^T (+epilogue) ----------------
// MODE 0: QKV scatter   out[((win*12+head)*49+tok)*96 + t] = v + bias[n]
// MODE 1: proj+residual out[xl*C + n] = res[xl*C+n] + v + bias[n]   (row remap window->BL)
// MODE 2: FC1 + GELU    out[m*N + n] = gelu(v + bias[n])
// MODE 3: FC2+residual  out[m*N + n] = res[m*N+n] + v + bias[n]
template<int MODE>
__global__ void __launch_bounds__(256)
gemm64(const float* __restrict__ A, const float* __restrict__ W,
       const float* __restrict__ bias, float* __restrict__ out,
       int M, int Ncols, int K, const float* __restrict__ res)
{
    __shared__ float As[16][65];
    __shared__ float Bs[16][65];
    int m0 = blockIdx.y * 64, n0 = blockIdx.x * 64;
    int tid = threadIdx.x;
    int tx = tid & 15, ty = tid >> 4;
    int lr = tid >> 2;          // 0..63
    int lk = (tid & 3) * 4;     // 0,4,8,12
    float acc[4][4] = {};
    const float* Ap = A + (size_t)(m0 + lr) * K + lk;
    const float* Wp = W + (size_t)(n0 + lr) * K + lk;
    for (int k0 = 0; k0 < K; k0 += 16) {
        float4 av = *(const float4*)(Ap + k0);
        float4 bv = *(const float4*)(Wp + k0);
        As[lk + 0][lr] = av.x; As[lk + 1][lr] = av.y;
        As[lk + 2][lr] = av.z; As[lk + 3][lr] = av.w;
        Bs[lk + 0][lr] = bv.x; Bs[lk + 1][lr] = bv.y;
        Bs[lk + 2][lr] = bv.z; Bs[lk + 3][lr] = bv.w;
        __syncthreads();
#pragma unroll
        for (int k = 0; k < 16; k++) {
            float a[4], b[4];
#pragma unroll
            for (int i = 0; i < 4; i++) a[i] = As[k][ty * 4 + i];
#pragma unroll
            for (int j = 0; j < 4; j++) b[j] = Bs[k][tx * 4 + j];
#pragma unroll
            for (int i = 0; i < 4; i++)
#pragma unroll
                for (int j = 0; j < 4; j++)
                    acc[i][j] = fmaf(a[i], b[j], acc[i][j]);
        }
        __syncthreads();
    }
#pragma unroll
    for (int i = 0; i < 4; i++) {
        int m = m0 + ty * 4 + i;
#pragma unroll
        for (int j = 0; j < 4; j++) {
            int n = n0 + tx * 4 + j;
            float v = acc[i][j] + bias[n];
            if (MODE == 0) {
                int win = m / NTOK, tok = m % NTOK;
                int head = n / 96, t = n % 96;
                out[((size_t)(win * NHEAD + head) * NTOK + tok) * 96 + t] = v;
            } else if (MODE == 1) {
                int xl = win_row_to_xl(m);
                out[(size_t)xl * CDIM + n] = res[(size_t)xl * CDIM + n] + v;
            } else if (MODE == 2) {
                out[(size_t)m * Ncols + n] = 0.5f * v * (1.f + erff(v * 0.70710678118654752f));
            } else {
                out[(size_t)m * Ncols + n] = res[(size_t)m * Ncols + n] + v;
            }
        }
    }
}

// ---------------- attention: one block per (window, head) ----------------
__global__ void __launch_bounds__(256)
attn_kernel(const float* __restrict__ qkv, const float* __restrict__ attn_bias,
            const int* __restrict__ bias_idxs, float* __restrict__ o)
{
    int wh = blockIdx.x;                  // win*12 + head
    int win = wh / NHEAD, head = wh % NHEAD;
    const float* base = qkv + (size_t)wh * NTOK * 96;
    __shared__ float sq[NTOK][KDIM];
    __shared__ float sk[NTOK][KDIM];
    __shared__ float sv[NTOK][KDIM];
    __shared__ float sS[NTOK][NTOK + 1];
    __shared__ float sbias[NTOK];
    int tid = threadIdx.x;
    for (int i = tid; i < NTOK * 96; i += 256) {
        int n = i / 96, t = i % 96;
        float v = base[i];
        if (t < 32)      sq[n][t]      = v;
        else if (t < 64) sk[n][t - 32] = v;
        else             sv[n][t - 64] = v;
    }
    for (int i = tid; i < NTOK; i += 256) sbias[i] = attn_bias[head * NTOK + i];
    __syncthreads();
    const float scale = 0.1767766952966369f;   // 1/sqrt(32)
    for (int e = tid; e < NTOK * NTOK; e += 256) {
        int i = e / NTOK, j = e % NTOK;
        float s = 0.f;
#pragma unroll
        for (int d = 0; d < KDIM; d++) s = fmaf(sq[i][d], sk[j][d], s);
        sS[i][j] = s * scale + sbias[bias_idxs[e]];
    }
    __syncthreads();
    int warp = tid >> 5, lane = tid & 31;
    for (int i = warp; i < NTOK; i += 8) {
        float m = -1e30f;
        for (int j = lane; j < NTOK; j += 32) m = fmaxf(m, sS[i][j]);
#pragma unroll
        for (int off = 16; off; off >>= 1) m = fmaxf(m, __shfl_xor_sync(0xffffffffu, m, off));
        float sum = 0.f;
        for (int j = lane; j < NTOK; j += 32) {
            float e2 = __expf(sS[i][j] - m);
            sS[i][j] = e2;
            sum += e2;
        }
#pragma unroll
        for (int off = 16; off; off >>= 1) sum += __shfl_xor_sync(0xffffffffu, sum, off);
        float inv = 1.f / sum;
        for (int j = lane; j < NTOK; j += 32) sS[i][j] *= inv;
    }
    __syncthreads();
    for (int e = tid; e < NTOK * KDIM; e += 256) {
        int i = e / KDIM, d = e % KDIM;
        float s = 0.f;
#pragma unroll
        for (int j = 0; j < NTOK; j++) s = fmaf(sS[i][j], sv[j][d], s);
        o[((size_t)(win * NTOK + i)) * CDIM + head * KDIM + d] = s;
    }
}

// ---------------- depthwise 3x3 conv (SAME) + BN ----------------
__global__ void __launch_bounds__(128)
conv_bn_kernel(const float* __restrict__ x1, const float* __restrict__ cw,
               const float* __restrict__ bng, const float* __restrict__ bnb,
               const float* __restrict__ bnm, const float* __restrict__ bnv,
               float* __restrict__ x2)
{
    int bl = blockIdx.x;
    int b = bl / LDIM, l = bl % LDIM;
    int h = l / HDIM, w = l % HDIM;
    for (int c = threadIdx.x; c < CDIM; c += 128) {
        float s = 0.f;
#pragma unroll
        for (int dh = -1; dh <= 1; dh++) {
            int hh = h + dh;
            if (hh < 0 || hh >= HDIM) continue;
#pragma unroll
            for (int dw = -1; dw <= 1; dw++) {
                int ww = w + dw;
                if (ww < 0 || ww >= HDIM) continue;
                s = fmaf(x1[((size_t)b * LDIM + hh * HDIM + ww) * CDIM + c],
                         cw[c * 9 + (dh + 1) * 3 + (dw + 1)], s);
            }
        }
        float inv = rsqrtf(bnv[c] + 1e-5f);
        x2[(size_t)bl * CDIM + c] = (s - bnm[c]) * bng[c] * inv + bnb[c];
    }
}

// ---------------- launch ----------------
static float* symptr(const void* s) {
    void* p = nullptr;
    cudaGetSymbolAddress(&p, s);
    return (float*)p;
}

extern "C" void kernel_launch(void* const* d_in, const int* in_sizes, int n_in,
                              void* d_out, int out_size)
{
    const float* x        = (const float*)d_in[0];
    const float* ln_a_g   = (const float*)d_in[1];
    const float* ln_a_b   = (const float*)d_in[2];
    const float* qkv_w    = (const float*)d_in[3];
    const float* qkv_b    = (const float*)d_in[4];
    const float* attn_bias= (const float*)d_in[5];
    const float* proj_w   = (const float*)d_in[6];
    const float* proj_b   = (const float*)d_in[7];
    const float* conv_w   = (const float*)d_in[8];
    const float* bn_g     = (const float*)d_in[9];
    const float* bn_b     = (const float*)d_in[10];
    const float* bn_m     = (const float*)d_in[11];
    const float* bn_v     = (const float*)d_in[12];
    const float* ln_m_g   = (const float*)d_in[13];
    const float* ln_m_b   = (const float*)d_in[14];
    const float* fc1_w    = (const float*)d_in[15];
    const float* fc1_b    = (const float*)d_in[16];
    const float* fc2_w    = (const float*)d_in[17];
    const float* fc2_b    = (const float*)d_in[18];
    const int*   bias_idxs= (const int*)d_in[19];
    float* out = (float*)d_out;

    float* xn   = symptr(g_xn);
    float* qkv  = symptr(g_qkv);
    float* ob   = symptr(g_o);
    float* x1   = symptr(g_x1);
    float* x2   = symptr(g_x2);
    float* hmid = symptr(g_hmid);

    // 1. windowed LN
    ln_kernel<true><<<MROWS / 8, 256>>>(x, ln_a_g, ln_a_b, xn);
    // 2. QKV GEMM (scatter to [win,head,tok,96])
    gemm64<0><<<dim3(QKVO / 64, MROWS / 64), 256>>>(xn, qkv_w, qkv_b, qkv, MROWS, QKVO, CDIM, nullptr);
    // 3. attention
    attn_kernel<<<NWIN * NHEAD, 256>>>(qkv, attn_bias, bias_idxs, ob);
    // 4. proj GEMM + window reverse + residual -> x1 (B,L,C)
    gemm64<1><<<dim3(CDIM / 64, MROWS / 64), 256>>>(ob, proj_w, proj_b, x1, MROWS, CDIM, CDIM, x);
    // 5. depthwise conv + BN -> x2
    conv_bn_kernel<<<BDIM * LDIM, 128>>>(x1, conv_w, bn_g, bn_b, bn_m, bn_v, x2);
    // 6. LN -> xn (reuse)
    ln_kernel<false><<<MROWS / 8, 256>>>(x2, ln_m_g, ln_m_b, xn);
    // 7. FC1 + GELU
    gemm64<2><<<dim3(HIDD / 64, MROWS / 64), 256>>>(xn, fc1_w, fc1_b, hmid, MROWS, HIDD, CDIM, nullptr);
    // 8. FC2 + residual -> out
    gemm64<3><<<dim3(CDIM / 64, MROWS / 64), 256>>>(hmid, fc2_w, fc2_b, out, MROWS, CDIM, HIDD, x2);
}

// round 2
// speedup vs baseline: 2.2536x; 2.2536x over previous
#include <cuda_runtime.h>
#include <math.h>
#include <stdint.h>

#define WSZ 7
#define NTOK 49
#define CDIM 384
#define NHEAD 12
#define KDIM 32
#define BDIM 64
#define HDIM 28
#define LDIM 784
#define HIDD 1536
#define NWIN 1024
#define MROWS 50176
#define QKVO 1152

// ---------------- scratch (device globals; allocation-free) ----------------
__device__ float g_xn[(size_t)MROWS * CDIM];
__device__ float g_qkv[(size_t)MROWS * QKVO];    // [win, head, tok, 96]
__device__ float g_o[(size_t)MROWS * CDIM];      // attention output (window order)
__device__ float g_x1[(size_t)MROWS * CDIM];     // after attn residual (B,L,C)
__device__ float g_x2[(size_t)MROWS * CDIM];     // after conv+BN (B,L,C)
__device__ float g_hmid[(size_t)MROWS * HIDD];   // MLP hidden

__device__ __forceinline__ int win_row_to_xl(int r) {
    int win = r / NTOK, n = r % NTOK;
    int b = win >> 4;
    int wh = (win >> 2) & 3, ww = win & 3;
    int ih = n / WSZ, iw = n % WSZ;
    int h = wh * WSZ + ih, w = ww * WSZ + iw;
    return b * LDIM + h * HDIM + w;
}

__device__ __forceinline__ uint32_t f2tf32(float f) {
    uint32_t r;
    asm("cvt.rna.tf32.f32 %0, %1;" : "=r"(r) : "f"(f));
    return r;
}

__device__ __forceinline__ void mma_tf32(float c[4], uint32_t a0, uint32_t a1,
                                         uint32_t a2, uint32_t a3,
                                         uint32_t b0, uint32_t b1) {
    asm volatile(
        "mma.sync.aligned.m16n8k8.row.col.f32.tf32.tf32.f32 "
        "{%0,%1,%2,%3}, {%4,%5,%6,%7}, {%8,%9}, {%0,%1,%2,%3};"
        : "+f"(c[0]), "+f"(c[1]), "+f"(c[2]), "+f"(c[3])
        : "r"(a0), "r"(a1), "r"(a2), "r"(a3), "r"(b0), "r"(b1));
}

// ---------------- LayerNorm: one warp per row ----------------
template<bool WINDOWED>
__global__ void __launch_bounds__(256)
ln_kernel(const float* __restrict__ x, const float* __restrict__ g,
          const float* __restrict__ bvec, float* __restrict__ out)
{
    int r = blockIdx.x * 8 + (threadIdx.x >> 5);
    int lane = threadIdx.x & 31;
    if (r >= MROWS) return;
    int src_row = WINDOWED ? win_row_to_xl(r) : r;
    const float* src = x + (size_t)src_row * CDIM;
    float vals[12];
    float s = 0.f, s2 = 0.f;
#pragma unroll
    for (int i = 0; i < 12; i++) {
        float v = src[lane + 32 * i];
        vals[i] = v;
        s += v;
        s2 = fmaf(v, v, s2);
    }
#pragma unroll
    for (int o = 16; o; o >>= 1) {
        s  += __shfl_xor_sync(0xffffffffu, s,  o);
        s2 += __shfl_xor_sync(0xffffffffu, s2, o);
    }
    float mean = s * (1.f / CDIM);
    float var  = s2 * (1.f / CDIM) - mean * mean;
    float inv  = rsqrtf(var + 1e-5f);
    float* dst = out + (size_t)r * CDIM;
#pragma unroll
    for (int i = 0; i < 12; i++) {
        int c = lane + 32 * i;
        dst[c] = (vals[i] - mean) * inv * g[c] + bvec[c];
    }
}

// ------- tensor-core tf32 GEMM: out = A(MxK) * W(NxK)^T (+epilogue) -------
// CTA tile 128x128, BK=32, 8 warps (2x4), warp tile 64x32 = 4x4 m16n8k8.
// MODE 0: QKV scatter  MODE 1: proj+res (win->BL remap)  MODE 2: FC1+GELU
// MODE 3: FC2+res
#define PADM 136
template<int MODE>
__global__ void __launch_bounds__(256)
gemm_tc(const float* __restrict__ A, const float* __restrict__ W,
        const float* __restrict__ bias, float* __restrict__ out,
        int M, int Ncols, int K, const float* __restrict__ res)
{
    __shared__ uint32_t As[32][PADM];
    __shared__ uint32_t Bs[32][PADM];
    int tid  = threadIdx.x;
    int warp = tid >> 5, lane = tid & 31;
    int wm = warp >> 2;           // 0..1  (m offset wm*64)
    int wn = warp & 3;            // 0..3  (n offset wn*32)
    int m0 = blockIdx.y * 128, n0 = blockIdx.x * 128;

    int lr = tid >> 1;            // 0..127 load row
    int cs = (tid & 1) * 16;      // col seg base (0 or 16)

    float acc[4][4][4];
#pragma unroll
    for (int mt = 0; mt < 4; mt++)
#pragma unroll
        for (int nt = 0; nt < 4; nt++)
#pragma unroll
            for (int i = 0; i < 4; i++) acc[mt][nt][i] = 0.f;

    const int qr = lane >> 2, qc = lane & 3;   // fragment row/col helpers

    for (int k0 = 0; k0 < K; k0 += 32) {
        // global -> smem (transposed, tf32-converted)
        const float* Ap = A + (size_t)(m0 + lr) * K + k0 + cs;
        const float* Wp = W + (size_t)(n0 + lr) * K + k0 + cs;
#pragma unroll
        for (int q = 0; q < 4; q++) {
            float4 av = *(const float4*)(Ap + 4 * q);
            float4 bv = *(const float4*)(Wp + 4 * q);
            int kk = cs + 4 * q;
            As[kk + 0][lr] = f2tf32(av.x); As[kk + 1][lr] = f2tf32(av.y);
            As[kk + 2][lr] = f2tf32(av.z); As[kk + 3][lr] = f2tf32(av.w);
            Bs[kk + 0][lr] = f2tf32(bv.x); Bs[kk + 1][lr] = f2tf32(bv.y);
            Bs[kk + 2][lr] = f2tf32(bv.z); Bs[kk + 3][lr] = f2tf32(bv.w);
        }
        __syncthreads();
#pragma unroll
        for (int ks = 0; ks < 4; ks++) {
            int kb = ks * 8;
            uint32_t af[4][4];
#pragma unroll
            for (int mt = 0; mt < 4; mt++) {
                int mb = wm * 64 + mt * 16;
                af[mt][0] = As[kb + qc    ][mb + qr    ];
                af[mt][1] = As[kb + qc    ][mb + qr + 8];
                af[mt][2] = As[kb + qc + 4][mb + qr    ];
                af[mt][3] = As[kb + qc + 4][mb + qr + 8];
            }
            uint32_t bf[4][2];
#pragma unroll
            for (int nt = 0; nt < 4; nt++) {
                int nb = wn * 32 + nt * 8;
                bf[nt][0] = Bs[kb + qc    ][nb + qr];
                bf[nt][1] = Bs[kb + qc + 4][nb + qr];
            }
#pragma unroll
            for (int mt = 0; mt < 4; mt++)
#pragma unroll
                for (int nt = 0; nt < 4; nt++)
                    mma_tf32(acc[mt][nt], af[mt][0], af[mt][1], af[mt][2], af[mt][3],
                             bf[nt][0], bf[nt][1]);
        }
        __syncthreads();
    }

    // epilogue
#pragma unroll
    for (int mt = 0; mt < 4; mt++) {
#pragma unroll
        for (int nt = 0; nt < 4; nt++) {
#pragma unroll
            for (int i = 0; i < 4; i++) {
                int m = m0 + wm * 64 + mt * 16 + qr + (i >> 1) * 8;
                int n = n0 + wn * 32 + nt * 8 + qc * 2 + (i & 1);
                float v = acc[mt][nt][i] + bias[n];
                if (MODE == 0) {
                    int win = m / NTOK, tok = m % NTOK;
                    int head = n / 96, t = n % 96;
                    out[((size_t)(win * NHEAD + head) * NTOK + tok) * 96 + t] = v;
                } else if (MODE == 1) {
                    int xl = win_row_to_xl(m);
                    out[(size_t)xl * CDIM + n] = res[(size_t)xl * CDIM + n] + v;
                } else if (MODE == 2) {
                    out[(size_t)m * Ncols + n] =
                        0.5f * v * (1.f + erff(v * 0.70710678118654752f));
                } else {
                    out[(size_t)m * Ncols + n] = res[(size_t)m * Ncols + n] + v;
                }
            }
        }
    }
}

// ---------------- attention: one block per (window, head) ----------------
__global__ void __launch_bounds__(256)
attn_kernel(const float* __restrict__ qkv, const float* __restrict__ attn_bias,
            const int* __restrict__ bias_idxs, float* __restrict__ o)
{
    int wh = blockIdx.x;
    int win = wh / NHEAD, head = wh % NHEAD;
    const float* base = qkv + (size_t)wh * NTOK * 96;
    __shared__ float sq[NTOK][KDIM];
    __shared__ float sk[NTOK][KDIM];
    __shared__ float sv[NTOK][KDIM];
    __shared__ float sS[NTOK][NTOK + 1];
    __shared__ float sbias[NTOK];
    int tid = threadIdx.x;
    for (int i = tid; i < NTOK * 96; i += 256) {
        int n = i / 96, t = i % 96;
        float v = base[i];
        if (t < 32)      sq[n][t]      = v;
        else if (t < 64) sk[n][t - 32] = v;
        else             sv[n][t - 64] = v;
    }
    for (int i = tid; i < NTOK; i += 256) sbias[i] = attn_bias[head * NTOK + i];
    __syncthreads();
    const float scale = 0.1767766952966369f;
    for (int e = tid; e < NTOK * NTOK; e += 256) {
        int i = e / NTOK, j = e % NTOK;
        float s = 0.f;
#pragma unroll
        for (int d = 0; d < KDIM; d++) s = fmaf(sq[i][d], sk[j][d], s);
        sS[i][j] = s * scale + sbias[bias_idxs[e]];
    }
    __syncthreads();
    int warp = tid >> 5, lane = tid & 31;
    for (int i = warp; i < NTOK; i += 8) {
        float m = -1e30f;
        for (int j = lane; j < NTOK; j += 32) m = fmaxf(m, sS[i][j]);
#pragma unroll
        for (int off = 16; off; off >>= 1) m = fmaxf(m, __shfl_xor_sync(0xffffffffu, m, off));
        float sum = 0.f;
        for (int j = lane; j < NTOK; j += 32) {
            float e2 = __expf(sS[i][j] - m);
            sS[i][j] = e2;
            sum += e2;
        }
#pragma unroll
        for (int off = 16; off; off >>= 1) sum += __shfl_xor_sync(0xffffffffu, sum, off);
        float inv = 1.f / sum;
        for (int j = lane; j < NTOK; j += 32) sS[i][j] *= inv;
    }
    __syncthreads();
    for (int e = tid; e < NTOK * KDIM; e += 256) {
        int i = e / KDIM, d = e % KDIM;
        float s = 0.f;
#pragma unroll
        for (int j = 0; j < NTOK; j++) s = fmaf(sS[i][j], sv[j][d], s);
        o[((size_t)(win * NTOK + i)) * CDIM + head * KDIM + d] = s;
    }
}

// ---------------- depthwise 3x3 conv (SAME) + BN ----------------
__global__ void __launch_bounds__(128)
conv_bn_kernel(const float* __restrict__ x1, const float* __restrict__ cw,
               const float* __restrict__ bng, const float* __restrict__ bnb,
               const float* __restrict__ bnm, const float* __restrict__ bnv,
               float* __restrict__ x2)
{
    int bl = blockIdx.x;
    int b = bl / LDIM, l = bl % LDIM;
    int h = l / HDIM, w = l % HDIM;
    for (int c = threadIdx.x; c < CDIM; c += 128) {
        float s = 0.f;
#pragma unroll
        for (int dh = -1; dh <= 1; dh++) {
            int hh = h + dh;
            if (hh < 0 || hh >= HDIM) continue;
#pragma unroll
            for (int dw = -1; dw <= 1; dw++) {
                int ww = w + dw;
                if (ww < 0 || ww >= HDIM) continue;
                s = fmaf(x1[((size_t)b * LDIM + hh * HDIM + ww) * CDIM + c],
                         cw[c * 9 + (dh + 1) * 3 + (dw + 1)], s);
            }
        }
        float inv = rsqrtf(bnv[c] + 1e-5f);
        x2[(size_t)bl * CDIM + c] = (s - bnm[c]) * bng[c] * inv + bnb[c];
    }
}

// ---------------- launch ----------------
static float* symptr(const void* s) {
    void* p = nullptr;
    cudaGetSymbolAddress(&p, s);
    return (float*)p;
}

extern "C" void kernel_launch(void* const* d_in, const int* in_sizes, int n_in,
                              void* d_out, int out_size)
{
    const float* x        = (const float*)d_in[0];
    const float* ln_a_g   = (const float*)d_in[1];
    const float* ln_a_b   = (const float*)d_in[2];
    const float* qkv_w    = (const float*)d_in[3];
    const float* qkv_b    = (const float*)d_in[4];
    const float* attn_bias= (const float*)d_in[5];
    const float* proj_w   = (const float*)d_in[6];
    const float* proj_b   = (const float*)d_in[7];
    const float* conv_w   = (const float*)d_in[8];
    const float* bn_g     = (const float*)d_in[9];
    const float* bn_b     = (const float*)d_in[10];
    const float* bn_m     = (const float*)d_in[11];
    const float* bn_v     = (const float*)d_in[12];
    const float* ln_m_g   = (const float*)d_in[13];
    const float* ln_m_b   = (const float*)d_in[14];
    const float* fc1_w    = (const float*)d_in[15];
    const float* fc1_b    = (const float*)d_in[16];
    const float* fc2_w    = (const float*)d_in[17];
    const float* fc2_b    = (const float*)d_in[18];
    const int*   bias_idxs= (const int*)d_in[19];
    float* out = (float*)d_out;

    float* xn   = symptr(g_xn);
    float* qkv  = symptr(g_qkv);
    float* ob   = symptr(g_o);
    float* x1   = symptr(g_x1);
    float* x2   = symptr(g_x2);
    float* hmid = symptr(g_hmid);

    ln_kernel<true><<<MROWS / 8, 256>>>(x, ln_a_g, ln_a_b, xn);
    gemm_tc<0><<<dim3(QKVO / 128, MROWS / 128), 256>>>(xn, qkv_w, qkv_b, qkv, MROWS, QKVO, CDIM, nullptr);
    attn_kernel<<<NWIN * NHEAD, 256>>>(qkv, attn_bias, bias_idxs, ob);
    gemm_tc<1><<<dim3(CDIM / 128, MROWS / 128), 256>>>(ob, proj_w, proj_b, x1, MROWS, CDIM, CDIM, x);
    conv_bn_kernel<<<BDIM * LDIM, 128>>>(x1, conv_w, bn_g, bn_b, bn_m, bn_v, x2);
    ln_kernel<false><<<MROWS / 8, 256>>>(x2, ln_m_g, ln_m_b, xn);
    gemm_tc<2><<<dim3(HIDD / 128, MROWS / 128), 256>>>(xn, fc1_w, fc1_b, hmid, MROWS, HIDD, CDIM, nullptr);
    gemm_tc<3><<<dim3(CDIM / 128, MROWS / 128), 256>>>(hmid, fc2_w, fc2_b, out, MROWS, CDIM, HIDD, x2);
}

// round 3
// speedup vs baseline: 2.7587x; 1.2241x over previous
#include <cuda_runtime.h>
#include <math.h>
#include <stdint.h>

#define WSZ 7
#define NTOK 49
#define CDIM 384
#define NHEAD 12
#define KDIM 32
#define BDIM 64
#define HDIM 28
#define LDIM 784
#define HIDD 1536
#define NWIN 1024
#define MROWS 50176
#define QKVO 1152

// ---------------- scratch (device globals; allocation-free) ----------------
__device__ float g_xn[(size_t)MROWS * CDIM];
__device__ float g_qkv[(size_t)MROWS * QKVO];    // [win, head, tok, 96]
__device__ float g_o[(size_t)MROWS * CDIM];      // attention out (window order, tf32-rounded)
__device__ float g_x1[(size_t)MROWS * CDIM];     // after attn residual (B,L,C)
__device__ float g_x2[(size_t)MROWS * CDIM];     // after conv+BN (B,L,C)
__device__ float g_hmid[(size_t)MROWS * HIDD];   // MLP hidden (tf32-rounded)
__device__ float g_wrnd[442368 + 147456 + 589824 + 589824]; // rounded weights

__device__ __forceinline__ int win_row_to_xl(int r) {
    int win = r / NTOK, n = r % NTOK;
    int b = win >> 4;
    int wh = (win >> 2) & 3, ww = win & 3;
    int ih = n / WSZ, iw = n % WSZ;
    int h = wh * WSZ + ih, w = ww * WSZ + iw;
    return b * LDIM + h * HDIM + w;
}

__device__ __forceinline__ float tf32r(float f) {
    uint32_t r;
    asm("cvt.rna.tf32.f32 %0, %1;" : "=r"(r) : "f"(f));
    return __uint_as_float(r);
}

__device__ __forceinline__ void mma_tf32(float c[4], uint32_t a0, uint32_t a1,
                                         uint32_t a2, uint32_t a3,
                                         uint32_t b0, uint32_t b1) {
    asm volatile(
        "mma.sync.aligned.m16n8k8.row.col.f32.tf32.tf32.f32 "
        "{%0,%1,%2,%3}, {%4,%5,%6,%7}, {%8,%9}, {%0,%1,%2,%3};"
        : "+f"(c[0]), "+f"(c[1]), "+f"(c[2]), "+f"(c[3])
        : "r"(a0), "r"(a1), "r"(a2), "r"(a3), "r"(b0), "r"(b1));
}

__device__ __forceinline__ void cp16(void* dst, const void* src) {
    uint32_t d = (uint32_t)__cvta_generic_to_shared(dst);
    asm volatile("cp.async.cg.shared.global [%0], [%1], 16;" :: "r"(d), "l"(src));
}
__device__ __forceinline__ void cp_commit() { asm volatile("cp.async.commit_group;"); }
template<int N> __device__ __forceinline__ void cp_wait() {
    asm volatile("cp.async.wait_group %0;" :: "n"(N));
}

// ---------------- weight tf32 pre-round ----------------
__global__ void __launch_bounds__(256)
round_kernel(const float* __restrict__ in, float* __restrict__ out, int n) {
    int i = blockIdx.x * 256 + threadIdx.x;
    if (i < n) out[i] = tf32r(in[i]);
}

// ---------------- LayerNorm (tf32-rounded output) ----------------
template<bool WINDOWED>
__global__ void __launch_bounds__(256)
ln_kernel(const float* __restrict__ x, const float* __restrict__ g,
          const float* __restrict__ bvec, float* __restrict__ out)
{
    int r = blockIdx.x * 8 + (threadIdx.x >> 5);
    int lane = threadIdx.x & 31;
    if (r >= MROWS) return;
    int src_row = WINDOWED ? win_row_to_xl(r) : r;
    const float* src = x + (size_t)src_row * CDIM;
    float vals[12];
    float s = 0.f, s2 = 0.f;
#pragma unroll
    for (int i = 0; i < 12; i++) {
        float v = src[lane + 32 * i];
        vals[i] = v;
        s += v;
        s2 = fmaf(v, v, s2);
    }
#pragma unroll
    for (int o = 16; o; o >>= 1) {
        s  += __shfl_xor_sync(0xffffffffu, s,  o);
        s2 += __shfl_xor_sync(0xffffffffu, s2, o);
    }
    float mean = s * (1.f / CDIM);
    float var  = s2 * (1.f / CDIM) - mean * mean;
    float inv  = rsqrtf(var + 1e-5f);
    float* dst = out + (size_t)r * CDIM;
#pragma unroll
    for (int i = 0; i < 12; i++) {
        int c = lane + 32 * i;
        dst[c] = tf32r((vals[i] - mean) * inv * g[c] + bvec[c]);
    }
}

// ------- tensor-core tf32 GEMM v2: CTA 256x128x32, 2-stage cp.async -------
// 8 warps (4m x 2n), warp tile 64x64 = 4x8 m16n8k8 tiles.
// Inputs MUST be pre-rounded to tf32.
// MODE 0: QKV scatter  MODE 1: proj+res (win->BL remap)  MODE 2: FC1+GELU(round)
// MODE 3: FC2+res
#define APAD 36
template<int MODE>
__global__ void __launch_bounds__(256)
gemm_tc(const float* __restrict__ A, const float* __restrict__ W,
        const float* __restrict__ bias, float* __restrict__ out,
        int K, int Ncols, const float* __restrict__ res)
{
    extern __shared__ float smem[];
    float* As = smem;                       // 2 x 256 x 36
    float* Bs = smem + 2 * 256 * APAD;      // 2 x 128 x 36
    const int tid  = threadIdx.x;
    const int warp = tid >> 5, lane = tid & 31;
    const int wm = warp >> 1, wn = warp & 1;
    const int qr = lane >> 2, qc = lane & 3;
    const int m0 = blockIdx.y * 256, n0 = blockIdx.x * 128;

    const int rowb = tid >> 3;          // 0..31
    const int kq   = (tid & 7) * 4;     // 0,4,..28
    const float* Ag = A + (size_t)(m0 + rowb) * K + kq;
    const float* Wg = W + (size_t)(n0 + rowb) * K + kq;

    float acc[4][8][4] = {};

    // prefetch stage 0
    {
        float* Ad = As + rowb * APAD + kq;
        float* Bd = Bs + rowb * APAD + kq;
#pragma unroll
        for (int i = 0; i < 8; i++) cp16(Ad + i * 32 * APAD, Ag + (size_t)i * 32 * K);
#pragma unroll
        for (int i = 0; i < 4; i++) cp16(Bd + i * 32 * APAD, Wg + (size_t)i * 32 * K);
        cp_commit();
    }
    const int niter = K >> 5;
    for (int it = 0; it < niter; it++) {
        int cur = it & 1, nxt = cur ^ 1;
        if (it + 1 < niter) {
            int k0n = (it + 1) << 5;
            float* Ad = As + (nxt * 256 + rowb) * APAD + kq;
            float* Bd = Bs + (nxt * 128 + rowb) * APAD + kq;
#pragma unroll
            for (int i = 0; i < 8; i++) cp16(Ad + i * 32 * APAD, Ag + k0n + (size_t)i * 32 * K);
#pragma unroll
            for (int i = 0; i < 4; i++) cp16(Bd + i * 32 * APAD, Wg + k0n + (size_t)i * 32 * K);
            cp_commit();
            cp_wait<1>();
        } else {
            cp_wait<0>();
        }
        __syncthreads();
        const float* Ab = As + (cur * 256 + wm * 64) * APAD;
        const float* Bb = Bs + (cur * 128 + wn * 64) * APAD;
#pragma unroll
        for (int ks = 0; ks < 4; ks++) {
            int kb = ks * 8;
            uint32_t af[4][4], bf[8][2];
#pragma unroll
            for (int mt = 0; mt < 4; mt++) {
                const float* p = Ab + (mt * 16 + qr) * APAD + kb + qc;
                af[mt][0] = *(const uint32_t*)(p);
                af[mt][1] = *(const uint32_t*)(p + 8 * APAD);
                af[mt][2] = *(const uint32_t*)(p + 4);
                af[mt][3] = *(const uint32_t*)(p + 8 * APAD + 4);
            }
#pragma unroll
            for (int nt = 0; nt < 8; nt++) {
                const float* p = Bb + (nt * 8 + qr) * APAD + kb + qc;
                bf[nt][0] = *(const uint32_t*)(p);
                bf[nt][1] = *(const uint32_t*)(p + 4);
            }
#pragma unroll
            for (int mt = 0; mt < 4; mt++)
#pragma unroll
                for (int nt = 0; nt < 8; nt++)
                    mma_tf32(acc[mt][nt], af[mt][0], af[mt][1], af[mt][2], af[mt][3],
                             bf[nt][0], bf[nt][1]);
        }
        __syncthreads();
    }

    // epilogue
#pragma unroll
    for (int mt = 0; mt < 4; mt++) {
#pragma unroll
        for (int nt = 0; nt < 8; nt++) {
#pragma unroll
            for (int i = 0; i < 4; i++) {
                int m = m0 + wm * 64 + mt * 16 + qr + (i >> 1) * 8;
                int n = n0 + wn * 64 + nt * 8 + qc * 2 + (i & 1);
                float v = acc[mt][nt][i] + bias[n];
                if (MODE == 0) {
                    int win = m / NTOK, tok = m % NTOK;
                    int head = n / 96, t = n % 96;
                    out[((size_t)(win * NHEAD + head) * NTOK + tok) * 96 + t] = v;
                } else if (MODE == 1) {
                    int xl = win_row_to_xl(m);
                    out[(size_t)xl * CDIM + n] = res[(size_t)xl * CDIM + n] + v;
                } else if (MODE == 2) {
                    float gg = 0.5f * v * (1.f + erff(v * 0.70710678118654752f));
                    out[(size_t)m * Ncols + n] = tf32r(gg);
                } else {
                    out[(size_t)m * Ncols + n] = res[(size_t)m * Ncols + n] + v;
                }
            }
        }
    }
}

// ---------------- attention: one block per (window, head) ----------------
__global__ void __launch_bounds__(256)
attn_kernel(const float* __restrict__ qkv, const float* __restrict__ attn_bias,
            const int* __restrict__ bias_idxs, float* __restrict__ o)
{
    int wh = blockIdx.x;
    int win = wh / NHEAD, head = wh % NHEAD;
    const float* base = qkv + (size_t)wh * NTOK * 96;
    __shared__ float sq[NTOK][KDIM];
    __shared__ float sk[NTOK][KDIM];
    __shared__ float sv[NTOK][KDIM];
    __shared__ float sS[NTOK][NTOK + 1];
    __shared__ float sbias[NTOK];
    int tid = threadIdx.x;
    for (int i = tid; i < NTOK * 96; i += 256) {
        int n = i / 96, t = i % 96;
        float v = base[i];
        if (t < 32)      sq[n][t]      = v;
        else if (t < 64) sk[n][t - 32] = v;
        else             sv[n][t - 64] = v;
    }
    for (int i = tid; i < NTOK; i += 256) sbias[i] = attn_bias[head * NTOK + i];
    __syncthreads();
    const float scale = 0.1767766952966369f;
    for (int e = tid; e < NTOK * NTOK; e += 256) {
        int i = e / NTOK, j = e % NTOK;
        float s = 0.f;
#pragma unroll
        for (int d = 0; d < KDIM; d++) s = fmaf(sq[i][d], sk[j][d], s);
        sS[i][j] = s * scale + sbias[bias_idxs[e]];
    }
    __syncthreads();
    int warp = tid >> 5, lane = tid & 31;
    for (int i = warp; i < NTOK; i += 8) {
        float m = -1e30f;
        for (int j = lane; j < NTOK; j += 32) m = fmaxf(m, sS[i][j]);
#pragma unroll
        for (int off = 16; off; off >>= 1) m = fmaxf(m, __shfl_xor_sync(0xffffffffu, m, off));
        float sum = 0.f;
        for (int j = lane; j < NTOK; j += 32) {
            float e2 = __expf(sS[i][j] - m);
            sS[i][j] = e2;
            sum += e2;
        }
#pragma unroll
        for (int off = 16; off; off >>= 1) sum += __shfl_xor_sync(0xffffffffu, sum, off);
        float inv = 1.f / sum;
        for (int j = lane; j < NTOK; j += 32) sS[i][j] *= inv;
    }
    __syncthreads();
    for (int e = tid; e < NTOK * KDIM; e += 256) {
        int i = e / KDIM, d = e % KDIM;
        float s = 0.f;
#pragma unroll
        for (int j = 0; j < NTOK; j++) s = fmaf(sS[i][j], sv[j][d], s);
        o[((size_t)(win * NTOK + i)) * CDIM + head * KDIM + d] = tf32r(s);
    }
}

// ---------------- depthwise 3x3 conv (SAME) + BN ----------------
__global__ void __launch_bounds__(128)
conv_bn_kernel(const float* __restrict__ x1, const float* __restrict__ cw,
               const float* __restrict__ bng, const float* __restrict__ bnb,
               const float* __restrict__ bnm, const float* __restrict__ bnv,
               float* __restrict__ x2)
{
    int bl = blockIdx.x;
    int b = bl / LDIM, l = bl % LDIM;
    int h = l / HDIM, w = l % HDIM;
    for (int c = threadIdx.x; c < CDIM; c += 128) {
        float s = 0.f;
#pragma unroll
        for (int dh = -1; dh <= 1; dh++) {
            int hh = h + dh;
            if (hh < 0 || hh >= HDIM) continue;
#pragma unroll
            for (int dw = -1; dw <= 1; dw++) {
                int ww = w + dw;
                if (ww < 0 || ww >= HDIM) continue;
                s = fmaf(x1[((size_t)b * LDIM + hh * HDIM + ww) * CDIM + c],
                         cw[c * 9 + (dh + 1) * 3 + (dw + 1)], s);
            }
        }
        float inv = rsqrtf(bnv[c] + 1e-5f);
        x2[(size_t)bl * CDIM + c] = (s - bnm[c]) * bng[c] * inv + bnb[c];
    }
}

// ---------------- launch ----------------
static float* symptr(const void* s) {
    void* p = nullptr;
    cudaGetSymbolAddress(&p, s);
    return (float*)p;
}

#define GEMM_SMEM ((2 * 256 * APAD + 2 * 128 * APAD) * 4)

extern "C" void kernel_launch(void* const* d_in, const int* in_sizes, int n_in,
                              void* d_out, int out_size)
{
    const float* x        = (const float*)d_in[0];
    const float* ln_a_g   = (const float*)d_in[1];
    const float* ln_a_b   = (const float*)d_in[2];
    const float* qkv_w    = (const float*)d_in[3];
    const float* qkv_b    = (const float*)d_in[4];
    const float* attn_bias= (const float*)d_in[5];
    const float* proj_w   = (const float*)d_in[6];
    const float* proj_b   = (const float*)d_in[7];
    const float* conv_w   = (const float*)d_in[8];
    const float* bn_g     = (const float*)d_in[9];
    const float* bn_b     = (const float*)d_in[10];
    const float* bn_m     = (const float*)d_in[11];
    const float* bn_v     = (const float*)d_in[12];
    const float* ln_m_g   = (const float*)d_in[13];
    const float* ln_m_b   = (const float*)d_in[14];
    const float* fc1_w    = (const float*)d_in[15];
    const float* fc1_b    = (const float*)d_in[16];
    const float* fc2_w    = (const float*)d_in[17];
    const float* fc2_b    = (const float*)d_in[18];
    const int*   bias_idxs= (const int*)d_in[19];
    float* out = (float*)d_out;

    float* xn   = symptr(g_xn);
    float* qkv  = symptr(g_qkv);
    float* ob   = symptr(g_o);
    float* x1   = symptr(g_x1);
    float* x2   = symptr(g_x2);
    float* hmid = symptr(g_hmid);
    float* wbuf = symptr(g_wrnd);

    float* wq  = wbuf;
    float* wp  = wq + 442368;
    float* w1  = wp + 147456;
    float* w2  = w1 + 589824;

    cudaFuncSetAttribute(gemm_tc<0>, cudaFuncAttributeMaxDynamicSharedMemorySize, GEMM_SMEM);
    cudaFuncSetAttribute(gemm_tc<1>, cudaFuncAttributeMaxDynamicSharedMemorySize, GEMM_SMEM);
    cudaFuncSetAttribute(gemm_tc<2>, cudaFuncAttributeMaxDynamicSharedMemorySize, GEMM_SMEM);
    cudaFuncSetAttribute(gemm_tc<3>, cudaFuncAttributeMaxDynamicSharedMemorySize, GEMM_SMEM);

    // pre-round weights to tf32
    round_kernel<<<(442368 + 255) / 256, 256>>>(qkv_w, wq, 442368);
    round_kernel<<<(147456 + 255) / 256, 256>>>(proj_w, wp, 147456);
    round_kernel<<<(589824 + 255) / 256, 256>>>(fc1_w, w1, 589824);
    round_kernel<<<(589824 + 255) / 256, 256>>>(fc2_w, w2, 589824);

    ln_kernel<true><<<MROWS / 8, 256>>>(x, ln_a_g, ln_a_b, xn);
    gemm_tc<0><<<dim3(QKVO / 128, MROWS / 256), 256, GEMM_SMEM>>>(xn, wq, qkv_b, qkv, CDIM, QKVO, nullptr);
    attn_kernel<<<NWIN * NHEAD, 256>>>(qkv, attn_bias, bias_idxs, ob);
    gemm_tc<1><<<dim3(CDIM / 128, MROWS / 256), 256, GEMM_SMEM>>>(ob, wp, proj_b, x1, CDIM, CDIM, x);
    conv_bn_kernel<<<BDIM * LDIM, 128>>>(x1, conv_w, bn_g, bn_b, bn_m, bn_v, x2);
    ln_kernel<false><<<MROWS / 8, 256>>>(x2, ln_m_g, ln_m_b, xn);
    gemm_tc<2><<<dim3(HIDD / 128, MROWS / 256), 256, GEMM_SMEM>>>(xn, w1, fc1_b, hmid, CDIM, HIDD, nullptr);
    gemm_tc<3><<<dim3(CDIM / 128, MROWS / 256), 256, GEMM_SMEM>>>(hmid, w2, fc2_b, out, HIDD, CDIM, x2);
}

// round 4
// speedup vs baseline: 3.1064x; 1.1260x over previous
#include <cuda_runtime.h>
#include <cuda_fp16.h>
#include <math.h>
#include <stdint.h>

#define WSZ 7
#define NTOK 49
#define CDIM 384
#define NHEAD 12
#define KDIM 32
#define BDIM 64
#define HDIM 28
#define LDIM 784
#define HIDD 1536
#define NWIN 1024
#define MROWS 50176
#define QKVO 1152

// ---------------- scratch ----------------
__device__ __half g_xn[(size_t)MROWS * CDIM];
__device__ __half g_qkv[(size_t)MROWS * QKVO];   // [win, head, tok, 96]
__device__ __half g_o[(size_t)MROWS * CDIM];     // attn out (window order)
__device__ float  g_x1[(size_t)MROWS * CDIM];    // after attn residual (B,L,C)
__device__ float  g_x2[(size_t)MROWS * CDIM];    // after conv+BN (B,L,C)
__device__ __half g_hmid[(size_t)MROWS * HIDD];  // MLP hidden
__device__ __half g_wh[442368 + 147456 + 589824 + 589824]; // half weights

__device__ __forceinline__ int win_row_to_xl(int r) {
    int win = r / NTOK, n = r % NTOK;
    int b = win >> 4;
    int wh = (win >> 2) & 3, ww = win & 3;
    int ih = n / WSZ, iw = n % WSZ;
    int h = wh * WSZ + ih, w = ww * WSZ + iw;
    return b * LDIM + h * HDIM + w;
}

__device__ __forceinline__ void mma_f16(float c[4], uint32_t a0, uint32_t a1,
                                        uint32_t a2, uint32_t a3,
                                        uint32_t b0, uint32_t b1) {
    asm volatile(
        "mma.sync.aligned.m16n8k16.row.col.f32.f16.f16.f32 "
        "{%0,%1,%2,%3}, {%4,%5,%6,%7}, {%8,%9}, {%0,%1,%2,%3};"
        : "+f"(c[0]), "+f"(c[1]), "+f"(c[2]), "+f"(c[3])
        : "r"(a0), "r"(a1), "r"(a2), "r"(a3), "r"(b0), "r"(b1));
}

__device__ __forceinline__ void cp16(void* dst, const void* src) {
    uint32_t d = (uint32_t)__cvta_generic_to_shared(dst);
    asm volatile("cp.async.cg.shared.global [%0], [%1], 16;" :: "r"(d), "l"(src));
}
__device__ __forceinline__ void cp_commit() { asm volatile("cp.async.commit_group;"); }
template<int N> __device__ __forceinline__ void cp_wait() {
    asm volatile("cp.async.wait_group %0;" :: "n"(N));
}
__device__ __forceinline__ void ldsm4(uint32_t& r0, uint32_t& r1, uint32_t& r2,
                                      uint32_t& r3, const void* p) {
    uint32_t a = (uint32_t)__cvta_generic_to_shared(p);
    asm volatile("ldmatrix.sync.aligned.m8n8.x4.shared.b16 {%0,%1,%2,%3}, [%4];"
                 : "=r"(r0), "=r"(r1), "=r"(r2), "=r"(r3) : "r"(a));
}
__device__ __forceinline__ void ldsm2(uint32_t& r0, uint32_t& r1, const void* p) {
    uint32_t a = (uint32_t)__cvta_generic_to_shared(p);
    asm volatile("ldmatrix.sync.aligned.m8n8.x2.shared.b16 {%0,%1}, [%2];"
                 : "=r"(r0), "=r"(r1) : "r"(a));
}

// ---------------- weight fp32 -> fp16 ----------------
__global__ void __launch_bounds__(256)
w2h_kernel(const float* __restrict__ in, __half* __restrict__ out, int n) {
    int i = blockIdx.x * 256 + threadIdx.x;
    if (i < n) out[i] = __float2half_rn(in[i]);
}

// ---------------- LayerNorm (half output) ----------------
template<bool WINDOWED>
__global__ void __launch_bounds__(256)
ln_kernel(const float* __restrict__ x, const float* __restrict__ g,
          const float* __restrict__ bvec, __half* __restrict__ out)
{
    int r = blockIdx.x * 8 + (threadIdx.x >> 5);
    int lane = threadIdx.x & 31;
    if (r >= MROWS) return;
    int src_row = WINDOWED ? win_row_to_xl(r) : r;
    const float* src = x + (size_t)src_row * CDIM;
    float vals[12];
    float s = 0.f, s2 = 0.f;
#pragma unroll
    for (int i = 0; i < 12; i++) {
        float v = src[lane + 32 * i];
        vals[i] = v;
        s += v;
        s2 = fmaf(v, v, s2);
    }
#pragma unroll
    for (int o = 16; o; o >>= 1) {
        s  += __shfl_xor_sync(0xffffffffu, s,  o);
        s2 += __shfl_xor_sync(0xffffffffu, s2, o);
    }
    float mean = s * (1.f / CDIM);
    float var  = s2 * (1.f / CDIM) - mean * mean;
    float inv  = rsqrtf(var + 1e-5f);
    __half* dst = out + (size_t)r * CDIM;
#pragma unroll
    for (int i = 0; i < 12; i++) {
        int c = lane + 32 * i;
        dst[c] = __float2half_rn((vals[i] - mean) * inv * g[c] + bvec[c]);
    }
}

// ------- fp16 tensor-core GEMM: CTA 256x128x32, 2-stage cp.async, ldmatrix -------
// 8 warps (4m x 2n), warp tile 64x64 = 4x8 m16n8k16 tiles, BK=32 (2 ksteps).
// MODE 0: QKV scatter(half)  MODE 1: proj+res->f32  MODE 2: FC1+GELU(half)  MODE 3: FC2+res->f32
#define HP 40   // padded row length in halves (stride 80B; ldmatrix conflict-free)
template<int MODE>
__global__ void __launch_bounds__(256)
gemm_h(const __half* __restrict__ A, const __half* __restrict__ W,
       const float* __restrict__ bias, void* __restrict__ outv,
       int K, int Ncols, const float* __restrict__ res)
{
    extern __shared__ __half sm[];
    __half* As = sm;                    // 2 x 256 x HP
    __half* Bs = sm + 2 * 256 * HP;     // 2 x 128 x HP
    const int tid  = threadIdx.x;
    const int warp = tid >> 5, lane = tid & 31;
    const int wm = warp >> 1, wn = warp & 1;
    const int qr = lane >> 2, qc = lane & 3;
    const int m0 = blockIdx.y * 256, n0 = blockIdx.x * 128;

    const int rowb = tid >> 2;          // 0..63
    const int cseg = (tid & 3) * 8;     // halves: 0,8,16,24
    const __half* Ag = A + (size_t)(m0 + rowb) * K + cseg;
    const __half* Wg = W + (size_t)(n0 + rowb) * K + cseg;

    float acc[4][8][4] = {};

    {
        __half* Ad = As + rowb * HP + cseg;
        __half* Bd = Bs + rowb * HP + cseg;
#pragma unroll
        for (int i = 0; i < 4; i++) cp16(Ad + i * 64 * HP, Ag + (size_t)i * 64 * K);
#pragma unroll
        for (int i = 0; i < 2; i++) cp16(Bd + i * 64 * HP, Wg + (size_t)i * 64 * K);
        cp_commit();
    }
    const int niter = K >> 5;
    for (int it = 0; it < niter; it++) {
        int cur = it & 1, nxt = cur ^ 1;
        if (it + 1 < niter) {
            int k0n = (it + 1) << 5;
            __half* Ad = As + (nxt * 256 + rowb) * HP + cseg;
            __half* Bd = Bs + (nxt * 128 + rowb) * HP + cseg;
#pragma unroll
            for (int i = 0; i < 4; i++) cp16(Ad + i * 64 * HP, Ag + k0n + (size_t)i * 64 * K);
#pragma unroll
            for (int i = 0; i < 2; i++) cp16(Bd + i * 64 * HP, Wg + k0n + (size_t)i * 64 * K);
            cp_commit();
            cp_wait<1>();
        } else {
            cp_wait<0>();
        }
        __syncthreads();
        const __half* Ab = As + (cur * 256 + wm * 64) * HP;
        const __half* Bb = Bs + (cur * 128 + wn * 64) * HP;
#pragma unroll
        for (int ks = 0; ks < 2; ks++) {
            int kb = ks * 16;
            uint32_t af[4][4], bf[8][2];
#pragma unroll
            for (int mt = 0; mt < 4; mt++)
                ldsm4(af[mt][0], af[mt][1], af[mt][2], af[mt][3],
                      Ab + (mt * 16 + (lane & 15)) * HP + kb + (lane >> 4) * 8);
#pragma unroll
            for (int nt = 0; nt < 8; nt++)
                ldsm2(bf[nt][0], bf[nt][1],
                      Bb + (nt * 8 + (lane & 7)) * HP + kb + ((lane >> 3) & 1) * 8);
#pragma unroll
            for (int mt = 0; mt < 4; mt++)
#pragma unroll
                for (int nt = 0; nt < 8; nt++)
                    mma_f16(acc[mt][nt], af[mt][0], af[mt][1], af[mt][2], af[mt][3],
                            bf[nt][0], bf[nt][1]);
        }
        __syncthreads();
    }

#pragma unroll
    for (int mt = 0; mt < 4; mt++) {
#pragma unroll
        for (int nt = 0; nt < 8; nt++) {
#pragma unroll
            for (int i = 0; i < 4; i++) {
                int m = m0 + wm * 64 + mt * 16 + qr + (i >> 1) * 8;
                int n = n0 + wn * 64 + nt * 8 + qc * 2 + (i & 1);
                float v = acc[mt][nt][i] + bias[n];
                if (MODE == 0) {
                    int win = m / NTOK, tok = m % NTOK;
                    int head = n / 96, t = n % 96;
                    ((__half*)outv)[((size_t)(win * NHEAD + head) * NTOK + tok) * 96 + t] =
                        __float2half_rn(v);
                } else if (MODE == 1) {
                    int xl = win_row_to_xl(m);
                    ((float*)outv)[(size_t)xl * CDIM + n] = res[(size_t)xl * CDIM + n] + v;
                } else if (MODE == 2) {
                    float gg = 0.5f * v * (1.f + erff(v * 0.70710678118654752f));
                    ((__half*)outv)[(size_t)m * Ncols + n] = __float2half_rn(gg);
                } else {
                    ((float*)outv)[(size_t)m * Ncols + n] = res[(size_t)m * Ncols + n] + v;
                }
            }
        }
    }
}

// ---------------- attention: one block per (window, head) ----------------
__global__ void __launch_bounds__(256)
attn_kernel(const __half* __restrict__ qkv, const float* __restrict__ attn_bias,
            const int* __restrict__ bias_idxs, __half* __restrict__ o)
{
    int wh = blockIdx.x;
    int win = wh / NHEAD, head = wh % NHEAD;
    const __half* base = qkv + (size_t)wh * NTOK * 96;
    __shared__ float sq[NTOK][KDIM];
    __shared__ float sk[NTOK][KDIM];
    __shared__ float sv[NTOK][KDIM];
    __shared__ float sS[NTOK][NTOK + 1];
    __shared__ float sbias[NTOK];
    int tid = threadIdx.x;
    for (int i = tid; i < NTOK * 96; i += 256) {
        int n = i / 96, t = i % 96;
        float v = __half2float(base[i]);
        if (t < 32)      sq[n][t]      = v;
        else if (t < 64) sk[n][t - 32] = v;
        else             sv[n][t - 64] = v;
    }
    for (int i = tid; i < NTOK; i += 256) sbias[i] = attn_bias[head * NTOK + i];
    __syncthreads();
    const float scale = 0.1767766952966369f;
    for (int e = tid; e < NTOK * NTOK; e += 256) {
        int i = e / NTOK, j = e % NTOK;
        float s = 0.f;
#pragma unroll
        for (int d = 0; d < KDIM; d++) s = fmaf(sq[i][d], sk[j][d], s);
        sS[i][j] = s * scale + sbias[bias_idxs[e]];
    }
    __syncthreads();
    int warp = tid >> 5, lane = tid & 31;
    for (int i = warp; i < NTOK; i += 8) {
        float m = -1e30f;
        for (int j = lane; j < NTOK; j += 32) m = fmaxf(m, sS[i][j]);
#pragma unroll
        for (int off = 16; off; off >>= 1) m = fmaxf(m, __shfl_xor_sync(0xffffffffu, m, off));
        float sum = 0.f;
        for (int j = lane; j < NTOK; j += 32) {
            float e2 = __expf(sS[i][j] - m);
            sS[i][j] = e2;
            sum += e2;
        }
#pragma unroll
        for (int off = 16; off; off >>= 1) sum += __shfl_xor_sync(0xffffffffu, sum, off);
        float inv = 1.f / sum;
        for (int j = lane; j < NTOK; j += 32) sS[i][j] *= inv;
    }
    __syncthreads();
    for (int e = tid; e < NTOK * KDIM; e += 256) {
        int i = e / KDIM, d = e % KDIM;
        float s = 0.f;
#pragma unroll
        for (int j = 0; j < NTOK; j++) s = fmaf(sS[i][j], sv[j][d], s);
        o[((size_t)(win * NTOK + i)) * CDIM + head * KDIM + d] = __float2half_rn(s);
    }
}

// ---------------- depthwise 3x3 conv (SAME) + BN ----------------
__global__ void __launch_bounds__(128)
conv_bn_kernel(const float* __restrict__ x1, const float* __restrict__ cw,
               const float* __restrict__ bng, const float* __restrict__ bnb,
               const float* __restrict__ bnm, const float* __restrict__ bnv,
               float* __restrict__ x2)
{
    int bl = blockIdx.x;
    int b = bl / LDIM, l = bl % LDIM;
    int h = l / HDIM, w = l % HDIM;
    for (int c = threadIdx.x; c < CDIM; c += 128) {
        float s = 0.f;
#pragma unroll
        for (int dh = -1; dh <= 1; dh++) {
            int hh = h + dh;
            if (hh < 0 || hh >= HDIM) continue;
#pragma unroll
            for (int dw = -1; dw <= 1; dw++) {
                int ww = w + dw;
                if (ww < 0 || ww >= HDIM) continue;
                s = fmaf(x1[((size_t)b * LDIM + hh * HDIM + ww) * CDIM + c],
                         cw[c * 9 + (dh + 1) * 3 + (dw + 1)], s);
            }
        }
        float inv = rsqrtf(bnv[c] + 1e-5f);
        x2[(size_t)bl * CDIM + c] = (s - bnm[c]) * bng[c] * inv + bnb[c];
    }
}

// ---------------- launch ----------------
static void* symptr(const void* s) {
    void* p = nullptr;
    cudaGetSymbolAddress(&p, s);
    return p;
}

#define GEMM_SMEM ((2 * 256 * HP + 2 * 128 * HP) * 2)

extern "C" void kernel_launch(void* const* d_in, const int* in_sizes, int n_in,
                              void* d_out, int out_size)
{
    const float* x        = (const float*)d_in[0];
    const float* ln_a_g   = (const float*)d_in[1];
    const float* ln_a_b   = (const float*)d_in[2];
    const float* qkv_w    = (const float*)d_in[3];
    const float* qkv_b    = (const float*)d_in[4];
    const float* attn_bias= (const float*)d_in[5];
    const float* proj_w   = (const float*)d_in[6];
    const float* proj_b   = (const float*)d_in[7];
    const float* conv_w   = (const float*)d_in[8];
    const float* bn_g     = (const float*)d_in[9];
    const float* bn_b     = (const float*)d_in[10];
    const float* bn_m     = (const float*)d_in[11];
    const float* bn_v     = (const float*)d_in[12];
    const float* ln_m_g   = (const float*)d_in[13];
    const float* ln_m_b   = (const float*)d_in[14];
    const float* fc1_w    = (const float*)d_in[15];
    const float* fc1_b    = (const float*)d_in[16];
    const float* fc2_w    = (const float*)d_in[17];
    const float* fc2_b    = (const float*)d_in[18];
    const int*   bias_idxs= (const int*)d_in[19];
    float* out = (float*)d_out;

    __half* xn   = (__half*)symptr(g_xn);
    __half* qkv  = (__half*)symptr(g_qkv);
    __half* ob   = (__half*)symptr(g_o);
    float*  x1   = (float*)symptr(g_x1);
    float*  x2   = (float*)symptr(g_x2);
    __half* hmid = (__half*)symptr(g_hmid);
    __half* wbuf = (__half*)symptr(g_wh);

    __half* wq = wbuf;
    __half* wp = wq + 442368;
    __half* w1 = wp + 147456;
    __half* w2 = w1 + 589824;

    cudaFuncSetAttribute(gemm_h<0>, cudaFuncAttributeMaxDynamicSharedMemorySize, GEMM_SMEM);
    cudaFuncSetAttribute(gemm_h<1>, cudaFuncAttributeMaxDynamicSharedMemorySize, GEMM_SMEM);
    cudaFuncSetAttribute(gemm_h<2>, cudaFuncAttributeMaxDynamicSharedMemorySize, GEMM_SMEM);
    cudaFuncSetAttribute(gemm_h<3>, cudaFuncAttributeMaxDynamicSharedMemorySize, GEMM_SMEM);

    w2h_kernel<<<(442368 + 255) / 256, 256>>>(qkv_w, wq, 442368);
    w2h_kernel<<<(147456 + 255) / 256, 256>>>(proj_w, wp, 147456);
    w2h_kernel<<<(589824 + 255) / 256, 256>>>(fc1_w, w1, 589824);
    w2h_kernel<<<(589824 + 255) / 256, 256>>>(fc2_w, w2, 589824);

    ln_kernel<true><<<MROWS / 8, 256>>>(x, ln_a_g, ln_a_b, xn);
    gemm_h<0><<<dim3(QKVO / 128, MROWS / 256), 256, GEMM_SMEM>>>(xn, wq, qkv_b, qkv, CDIM, QKVO, nullptr);
    attn_kernel<<<NWIN * NHEAD, 256>>>(qkv, attn_bias, bias_idxs, ob);
    gemm_h<1><<<dim3(CDIM / 128, MROWS / 256), 256, GEMM_SMEM>>>(ob, wp, proj_b, x1, CDIM, CDIM, x);
    conv_bn_kernel<<<BDIM * LDIM, 128>>>(x1, conv_w, bn_g, bn_b, bn_m, bn_v, x2);
    ln_kernel<false><<<MROWS / 8, 256>>>(x2, ln_m_g, ln_m_b, xn);
    gemm_h<2><<<dim3(HIDD / 128, MROWS / 256), 256, GEMM_SMEM>>>(xn, w1, fc1_b, hmid, CDIM, HIDD, nullptr);
    gemm_h<3><<<dim3(CDIM / 128, MROWS / 256), 256, GEMM_SMEM>>>(hmid, w2, fc2_b, out, HIDD, CDIM, x2);
}

// round 6
// speedup vs baseline: 5.6064x; 1.8048x over previous
#include <cuda_runtime.h>
#include <cuda_fp16.h>
#include <math.h>
#include <stdint.h>

#define WSZ 7
#define NTOK 49
#define CDIM 384
#define NHEAD 12
#define KDIM 32
#define BDIM 64
#define HDIM 28
#define LDIM 784
#define HIDD 1536
#define NWIN 1024
#define MROWS 50176
#define QKVO 1152

// ---------------- scratch ----------------
__device__ __half g_xn[(size_t)MROWS * CDIM];
__device__ __half g_qkv[(size_t)MROWS * QKVO];   // [win, head, tok, 96]
__device__ __half g_o[(size_t)MROWS * CDIM];     // attn out (window order)
__device__ float  g_x1[(size_t)MROWS * CDIM];    // after attn residual (B,L,C)
__device__ float  g_x2[(size_t)MROWS * CDIM];    // after conv+BN (B,L,C)
__device__ __half g_hmid[(size_t)MROWS * HIDD];  // MLP hidden
__device__ __half g_wh[442368 + 147456 + 589824 + 589824]; // half weights
__device__ float  g_biasp[NHEAD * 64 * 64];      // padded bias table

__device__ __forceinline__ int win_row_to_xl(int r) {
    int win = r / NTOK, n = r % NTOK;
    int b = win >> 4;
    int wh = (win >> 2) & 3, ww = win & 3;
    int ih = n / WSZ, iw = n % WSZ;
    int h = wh * WSZ + ih, w = ww * WSZ + iw;
    return b * LDIM + h * HDIM + w;
}

__device__ __forceinline__ uint32_t h2u(__half2 h) {
    union { __half2 h; uint32_t u; } cv;
    cv.h = h;
    return cv.u;
}

__device__ __forceinline__ void mma_f16(float c[4], uint32_t a0, uint32_t a1,
                                        uint32_t a2, uint32_t a3,
                                        uint32_t b0, uint32_t b1) {
    asm volatile(
        "mma.sync.aligned.m16n8k16.row.col.f32.f16.f16.f32 "
        "{%0,%1,%2,%3}, {%4,%5,%6,%7}, {%8,%9}, {%0,%1,%2,%3};"
        : "+f"(c[0]), "+f"(c[1]), "+f"(c[2]), "+f"(c[3])
        : "r"(a0), "r"(a1), "r"(a2), "r"(a3), "r"(b0), "r"(b1));
}

__device__ __forceinline__ void cp16(void* dst, const void* src) {
    uint32_t d = (uint32_t)__cvta_generic_to_shared(dst);
    asm volatile("cp.async.cg.shared.global [%0], [%1], 16;" :: "r"(d), "l"(src));
}
__device__ __forceinline__ void cp_commit() { asm volatile("cp.async.commit_group;"); }
template<int N> __device__ __forceinline__ void cp_wait() {
    asm volatile("cp.async.wait_group %0;" :: "n"(N));
}
__device__ __forceinline__ void ldsm4(uint32_t& r0, uint32_t& r1, uint32_t& r2,
                                      uint32_t& r3, const void* p) {
    uint32_t a = (uint32_t)__cvta_generic_to_shared(p);
    asm volatile("ldmatrix.sync.aligned.m8n8.x4.shared.b16 {%0,%1,%2,%3}, [%4];"
                 : "=r"(r0), "=r"(r1), "=r"(r2), "=r"(r3) : "r"(a));
}
__device__ __forceinline__ void ldsm2(uint32_t& r0, uint32_t& r1, const void* p) {
    uint32_t a = (uint32_t)__cvta_generic_to_shared(p);
    asm volatile("ldmatrix.sync.aligned.m8n8.x2.shared.b16 {%0,%1}, [%2];"
                 : "=r"(r0), "=r"(r1) : "r"(a));
}

// ---------------- weight fp32 -> fp16 ----------------
__global__ void __launch_bounds__(256)
w2h_kernel(const float* __restrict__ in, __half* __restrict__ out, int n) {
    int i = blockIdx.x * 256 + threadIdx.x;
    if (i < n) out[i] = __float2half_rn(in[i]);
}

// ---------------- bias table expand (padded, -inf in pad cols) ----------------
__global__ void __launch_bounds__(256)
bias_prep(const float* __restrict__ attn_bias, const int* __restrict__ bias_idxs,
          float* __restrict__ biasp) {
    int h = blockIdx.x;
    for (int e = threadIdx.x; e < 4096; e += 256) {
        int i = e >> 6, j = e & 63;
        float v;
        if (j >= NTOK) v = -1e30f;
        else if (i >= NTOK) v = 0.f;
        else v = attn_bias[h * NTOK + bias_idxs[i * NTOK + j]];
        biasp[h * 4096 + e] = v;
    }
}

// ---------------- windowed LayerNorm (half output) ----------------
__global__ void __launch_bounds__(256)
ln_kernel(const float* __restrict__ x, const float* __restrict__ g,
          const float* __restrict__ bvec, __half* __restrict__ out)
{
    int r = blockIdx.x * 8 + (threadIdx.x >> 5);
    int lane = threadIdx.x & 31;
    if (r >= MROWS) return;
    const float* src = x + (size_t)win_row_to_xl(r) * CDIM;
    float vals[12];
    float s = 0.f, s2 = 0.f;
#pragma unroll
    for (int i = 0; i < 12; i++) {
        float v = src[lane + 32 * i];
        vals[i] = v;
        s += v;
        s2 = fmaf(v, v, s2);
    }
#pragma unroll
    for (int o = 16; o; o >>= 1) {
        s  += __shfl_xor_sync(0xffffffffu, s,  o);
        s2 += __shfl_xor_sync(0xffffffffu, s2, o);
    }
    float mean = s * (1.f / CDIM);
    float var  = s2 * (1.f / CDIM) - mean * mean;
    float inv  = rsqrtf(var + 1e-5f);
    __half* dst = out + (size_t)r * CDIM;
#pragma unroll
    for (int i = 0; i < 12; i++) {
        int c = lane + 32 * i;
        dst[c] = __float2half_rn((vals[i] - mean) * inv * g[c] + bvec[c]);
    }
}

// ------- fp16 tensor-core GEMM: CTA 256x128x32, 2-stage cp.async, ldmatrix -------
#define HP 40
template<int MODE>
__global__ void __launch_bounds__(256)
gemm_h(const __half* __restrict__ A, const __half* __restrict__ W,
       const float* __restrict__ bias, void* __restrict__ outv,
       int K, int Ncols, const float* __restrict__ res)
{
    extern __shared__ __half sm[];
    __half* As = sm;
    __half* Bs = sm + 2 * 256 * HP;
    const int tid  = threadIdx.x;
    const int warp = tid >> 5, lane = tid & 31;
    const int wm = warp >> 1, wn = warp & 1;
    const int qr = lane >> 2, qc = lane & 3;
    const int m0 = blockIdx.y * 256, n0 = blockIdx.x * 128;

    const int rowb = tid >> 2;
    const int cseg = (tid & 3) * 8;
    const __half* Ag = A + (size_t)(m0 + rowb) * K + cseg;
    const __half* Wg = W + (size_t)(n0 + rowb) * K + cseg;

    float acc[4][8][4] = {};

    {
        __half* Ad = As + rowb * HP + cseg;
        __half* Bd = Bs + rowb * HP + cseg;
#pragma unroll
        for (int i = 0; i < 4; i++) cp16(Ad + i * 64 * HP, Ag + (size_t)i * 64 * K);
#pragma unroll
        for (int i = 0; i < 2; i++) cp16(Bd + i * 64 * HP, Wg + (size_t)i * 64 * K);
        cp_commit();
    }
    const int niter = K >> 5;
    for (int it = 0; it < niter; it++) {
        int cur = it & 1, nxt = cur ^ 1;
        if (it + 1 < niter) {
            int k0n = (it + 1) << 5;
            __half* Ad = As + (nxt * 256 + rowb) * HP + cseg;
            __half* Bd = Bs + (nxt * 128 + rowb) * HP + cseg;
#pragma unroll
            for (int i = 0; i < 4; i++) cp16(Ad + i * 64 * HP, Ag + k0n + (size_t)i * 64 * K);
#pragma unroll
            for (int i = 0; i < 2; i++) cp16(Bd + i * 64 * HP, Wg + k0n + (size_t)i * 64 * K);
            cp_commit();
            cp_wait<1>();
        } else {
            cp_wait<0>();
        }
        __syncthreads();
        const __half* Ab = As + (cur * 256 + wm * 64) * HP;
        const __half* Bb = Bs + (cur * 128 + wn * 64) * HP;
#pragma unroll
        for (int ks = 0; ks < 2; ks++) {
            int kb = ks * 16;
            uint32_t af[4][4], bf[8][2];
#pragma unroll
            for (int mt = 0; mt < 4; mt++)
                ldsm4(af[mt][0], af[mt][1], af[mt][2], af[mt][3],
                      Ab + (mt * 16 + (lane & 15)) * HP + kb + (lane >> 4) * 8);
#pragma unroll
            for (int nt = 0; nt < 8; nt++)
                ldsm2(bf[nt][0], bf[nt][1],
                      Bb + (nt * 8 + (lane & 7)) * HP + kb + ((lane >> 3) & 1) * 8);
#pragma unroll
            for (int mt = 0; mt < 4; mt++)
#pragma unroll
                for (int nt = 0; nt < 8; nt++)
                    mma_f16(acc[mt][nt], af[mt][0], af[mt][1], af[mt][2], af[mt][3],
                            bf[nt][0], bf[nt][1]);
        }
        __syncthreads();
    }

#pragma unroll
    for (int mt = 0; mt < 4; mt++) {
#pragma unroll
        for (int nt = 0; nt < 8; nt++) {
#pragma unroll
            for (int i = 0; i < 4; i++) {
                int m = m0 + wm * 64 + mt * 16 + qr + (i >> 1) * 8;
                int n = n0 + wn * 64 + nt * 8 + qc * 2 + (i & 1);
                float v = acc[mt][nt][i] + bias[n];
                if (MODE == 0) {
                    int win = m / NTOK, tok = m % NTOK;
                    int head = n / 96, t = n % 96;
                    ((__half*)outv)[((size_t)(win * NHEAD + head) * NTOK + tok) * 96 + t] =
                        __float2half_rn(v);
                } else if (MODE == 1) {
                    int xl = win_row_to_xl(m);
                    ((float*)outv)[(size_t)xl * CDIM + n] = res[(size_t)xl * CDIM + n] + v;
                } else if (MODE == 2) {
                    float gg = 0.5f * v * (1.f + erff(v * 0.70710678118654752f));
                    ((__half*)outv)[(size_t)m * Ncols + n] = __float2half_rn(gg);
                } else {
                    ((float*)outv)[(size_t)m * Ncols + n] = res[(size_t)m * Ncols + n] + v;
                }
            }
        }
    }
}

// ---------------- tensor-core attention: one block per (win, head) ----------------
#define QP 40
#define VP 72
__global__ void __launch_bounds__(128)
attn_tc(const __half* __restrict__ qkv, const float* __restrict__ biasp,
        __half* __restrict__ o)
{
    int wh = blockIdx.x;
    int win = wh / NHEAD, head = wh % NHEAD;
    __shared__ __half Qs[64 * QP];
    __shared__ __half Ks[64 * QP];
    __shared__ __half Vt[32 * VP];
    int tid = threadIdx.x;

    for (int i = tid; i < 64 * QP / 2; i += 128) {
        ((uint32_t*)Qs)[i] = 0;
        ((uint32_t*)Ks)[i] = 0;
    }
    for (int i = tid; i < 32 * VP / 2; i += 128) ((uint32_t*)Vt)[i] = 0;
    __syncthreads();

    const uint4* src = (const uint4*)(qkv + (size_t)wh * NTOK * 96);
    for (int idx = tid; idx < 588; idx += 128) {   // 49*96/8
        uint4 v = src[idx];
        int row = idx / 12, seg = idx % 12;
        if (seg < 4)      *(uint4*)(Qs + row * QP + seg * 8) = v;
        else if (seg < 8) *(uint4*)(Ks + row * QP + (seg - 4) * 8) = v;
        else {
            int d0 = (seg - 8) * 8;
            __half h[8];
            *(uint4*)h = v;
#pragma unroll
            for (int t = 0; t < 8; t++) Vt[(d0 + t) * VP + row] = h[t];
        }
    }
    __syncthreads();

    int warp = tid >> 5, lane = tid & 31;
    int qr = lane >> 2, qc = lane & 3;

    // S = Q K^T  (warp owns 16 rows)
    float sc[8][4] = {};
#pragma unroll
    for (int ks = 0; ks < 2; ks++) {
        int kb = ks * 16;
        uint32_t a0, a1, a2, a3;
        ldsm4(a0, a1, a2, a3, Qs + (warp * 16 + (lane & 15)) * QP + kb + (lane >> 4) * 8);
#pragma unroll
        for (int nt = 0; nt < 8; nt++) {
            uint32_t b0, b1;
            ldsm2(b0, b1, Ks + (nt * 8 + (lane & 7)) * QP + kb + ((lane >> 3) & 1) * 8);
            mma_f16(sc[nt], a0, a1, a2, a3, b0, b1);
        }
    }

    // bias + softmax (rows r0 = warp*16+qr, r1 = r0+8)
    const float scale = 0.1767766952966369f;
    const float* bp = biasp + (head * 64 + warp * 16) * 64;
    float m0 = -1e30f, m1 = -1e30f;
#pragma unroll
    for (int nt = 0; nt < 8; nt++) {
        int col = nt * 8 + qc * 2;
        sc[nt][0] = fmaf(sc[nt][0], scale, bp[qr * 64 + col]);
        sc[nt][1] = fmaf(sc[nt][1], scale, bp[qr * 64 + col + 1]);
        sc[nt][2] = fmaf(sc[nt][2], scale, bp[(qr + 8) * 64 + col]);
        sc[nt][3] = fmaf(sc[nt][3], scale, bp[(qr + 8) * 64 + col + 1]);
        m0 = fmaxf(m0, fmaxf(sc[nt][0], sc[nt][1]));
        m1 = fmaxf(m1, fmaxf(sc[nt][2], sc[nt][3]));
    }
#pragma unroll
    for (int off = 1; off < 4; off <<= 1) {
        m0 = fmaxf(m0, __shfl_xor_sync(0xffffffffu, m0, off));
        m1 = fmaxf(m1, __shfl_xor_sync(0xffffffffu, m1, off));
    }
    float s0 = 0.f, s1 = 0.f;
#pragma unroll
    for (int nt = 0; nt < 8; nt++) {
        sc[nt][0] = __expf(sc[nt][0] - m0);
        sc[nt][1] = __expf(sc[nt][1] - m0);
        sc[nt][2] = __expf(sc[nt][2] - m1);
        sc[nt][3] = __expf(sc[nt][3] - m1);
        s0 += sc[nt][0] + sc[nt][1];
        s1 += sc[nt][2] + sc[nt][3];
    }
#pragma unroll
    for (int off = 1; off < 4; off <<= 1) {
        s0 += __shfl_xor_sync(0xffffffffu, s0, off);
        s1 += __shfl_xor_sync(0xffffffffu, s1, off);
    }
    float i0 = 1.f / s0, i1 = 1.f / s1;
    uint32_t p01[8], p23[8];
#pragma unroll
    for (int nt = 0; nt < 8; nt++) {
        p01[nt] = h2u(__floats2half2_rn(sc[nt][0] * i0, sc[nt][1] * i0));
        p23[nt] = h2u(__floats2half2_rn(sc[nt][2] * i1, sc[nt][3] * i1));
    }

    // O = P V   (K = 64 tokens, N = 32 dims)
    float oc[4][4] = {};
#pragma unroll
    for (int ks = 0; ks < 4; ks++) {
        uint32_t a0 = p01[2 * ks], a1 = p23[2 * ks];
        uint32_t a2 = p01[2 * ks + 1], a3 = p23[2 * ks + 1];
#pragma unroll
        for (int nt = 0; nt < 4; nt++) {
            uint32_t b0, b1;
            ldsm2(b0, b1, Vt + (nt * 8 + (lane & 7)) * VP + ks * 16 + ((lane >> 3) & 1) * 8);
            mma_f16(oc[nt], a0, a1, a2, a3, b0, b1);
        }
    }

    int r0 = warp * 16 + qr, r1 = r0 + 8;
#pragma unroll
    for (int nt = 0; nt < 4; nt++) {
        int col = head * KDIM + nt * 8 + qc * 2;
        if (r0 < NTOK)
            *(__half2*)&o[((size_t)(win * NTOK + r0)) * CDIM + col] =
                __floats2half2_rn(oc[nt][0], oc[nt][1]);
        if (r1 < NTOK)
            *(__half2*)&o[((size_t)(win * NTOK + r1)) * CDIM + col] =
                __floats2half2_rn(oc[nt][2], oc[nt][3]);
    }
}

// ---------------- depthwise conv + BN + LN (fused) ----------------
__global__ void __launch_bounds__(128)
conv_bn_ln(const float* __restrict__ x1, const float* __restrict__ cw,
           const float* __restrict__ bng, const float* __restrict__ bnb,
           const float* __restrict__ bnm, const float* __restrict__ bnv,
           const float* __restrict__ lng, const float* __restrict__ lnb,
           float* __restrict__ x2, __half* __restrict__ xn)
{
    int bl = blockIdx.x;
    int b = bl / LDIM, l = bl % LDIM;
    int h = l / HDIM, w = l % HDIM;
    float vals[3];
    float s = 0.f, s2 = 0.f;
#pragma unroll
    for (int q = 0; q < 3; q++) {
        int c = threadIdx.x + q * 128;
        float acc = 0.f;
#pragma unroll
        for (int dh = -1; dh <= 1; dh++) {
            int hh = h + dh;
            if (hh < 0 || hh >= HDIM) continue;
#pragma unroll
            for (int dw = -1; dw <= 1; dw++) {
                int ww = w + dw;
                if (ww < 0 || ww >= HDIM) continue;
                acc = fmaf(x1[((size_t)b * LDIM + hh * HDIM + ww) * CDIM + c],
                           cw[c * 9 + (dh + 1) * 3 + (dw + 1)], acc);
            }
        }
        float inv = rsqrtf(bnv[c] + 1e-5f);
        float v = (acc - bnm[c]) * bng[c] * inv + bnb[c];
        vals[q] = v;
        x2[(size_t)bl * CDIM + c] = v;
        s += v;
        s2 = fmaf(v, v, s2);
    }
    __shared__ float reds[4], reds2[4];
    int lane = threadIdx.x & 31, warp = threadIdx.x >> 5;
#pragma unroll
    for (int o = 16; o; o >>= 1) {
        s  += __shfl_xor_sync(0xffffffffu, s,  o);
        s2 += __shfl_xor_sync(0xffffffffu, s2, o);
    }
    if (lane == 0) { reds[warp] = s; reds2[warp] = s2; }
    __syncthreads();
    s  = reds[0] + reds[1] + reds[2] + reds[3];
    s2 = reds2[0] + reds2[1] + reds2[2] + reds2[3];
    float mean = s * (1.f / CDIM);
    float var  = s2 * (1.f / CDIM) - mean * mean;
    float inv  = rsqrtf(var + 1e-5f);
#pragma unroll
    for (int q = 0; q < 3; q++) {
        int c = threadIdx.x + q * 128;
        xn[(size_t)bl * CDIM + c] =
            __float2half_rn((vals[q] - mean) * inv * lng[c] + lnb[c]);
    }
}

// ---------------- launch ----------------
static void* symptr(const void* s) {
    void* p = nullptr;
    cudaGetSymbolAddress(&p, s);
    return p;
}

#define GEMM_SMEM ((2 * 256 * HP + 2 * 128 * HP) * 2)

extern "C" void kernel_launch(void* const* d_in, const int* in_sizes, int n_in,
                              void* d_out, int out_size)
{
    const float* x        = (const float*)d_in[0];
    const float* ln_a_g   = (const float*)d_in[1];
    const float* ln_a_b   = (const float*)d_in[2];
    const float* qkv_w    = (const float*)d_in[3];
    const float* qkv_b    = (const float*)d_in[4];
    const float* attn_bias= (const float*)d_in[5];
    const float* proj_w   = (const float*)d_in[6];
    const float* proj_b   = (const float*)d_in[7];
    const float* conv_w   = (const float*)d_in[8];
    const float* bn_g     = (const float*)d_in[9];
    const float* bn_b     = (const float*)d_in[10];
    const float* bn_m     = (const float*)d_in[11];
    const float* bn_v     = (const float*)d_in[12];
    const float* ln_m_g   = (const float*)d_in[13];
    const float* ln_m_b   = (const float*)d_in[14];
    const float* fc1_w    = (const float*)d_in[15];
    const float* fc1_b    = (const float*)d_in[16];
    const float* fc2_w    = (const float*)d_in[17];
    const float* fc2_b    = (const float*)d_in[18];
    const int*   bias_idxs= (const int*)d_in[19];
    float* out = (float*)d_out;

    __half* xn    = (__half*)symptr(g_xn);
    __half* qkv   = (__half*)symptr(g_qkv);
    __half* ob    = (__half*)symptr(g_o);
    float*  x1    = (float*)symptr(g_x1);
    float*  x2    = (float*)symptr(g_x2);
    __half* hmid  = (__half*)symptr(g_hmid);
    __half* wbuf  = (__half*)symptr(g_wh);
    float*  biasp = (float*)symptr(g_biasp);

    __half* wq = wbuf;
    __half* wp = wq + 442368;
    __half* w1 = wp + 147456;
    __half* w2 = w1 + 589824;

    cudaFuncSetAttribute(gemm_h<0>, cudaFuncAttributeMaxDynamicSharedMemorySize, GEMM_SMEM);
    cudaFuncSetAttribute(gemm_h<1>, cudaFuncAttributeMaxDynamicSharedMemorySize, GEMM_SMEM);
    cudaFuncSetAttribute(gemm_h<2>, cudaFuncAttributeMaxDynamicSharedMemorySize, GEMM_SMEM);
    cudaFuncSetAttribute(gemm_h<3>, cudaFuncAttributeMaxDynamicSharedMemorySize, GEMM_SMEM);

    w2h_kernel<<<(442368 + 255) / 256, 256>>>(qkv_w, wq, 442368);
    w2h_kernel<<<(147456 + 255) / 256, 256>>>(proj_w, wp, 147456);
    w2h_kernel<<<(589824 + 255) / 256, 256>>>(fc1_w, w1, 589824);
    w2h_kernel<<<(589824 + 255) / 256, 256>>>(fc2_w, w2, 589824);
    bias_prep<<<NHEAD, 256>>>(attn_bias, bias_idxs, biasp);

    ln_kernel<<<MROWS / 8, 256>>>(x, ln_a_g, ln_a_b, xn);
    gemm_h<0><<<dim3(QKVO / 128, MROWS / 256), 256, GEMM_SMEM>>>(xn, wq, qkv_b, qkv, CDIM, QKVO, nullptr);
    attn_tc<<<NWIN * NHEAD, 128>>>(qkv, biasp, ob);
    gemm_h<1><<<dim3(CDIM / 128, MROWS / 256), 256, GEMM_SMEM>>>(ob, wp, proj_b, x1, CDIM, CDIM, x);
    conv_bn_ln<<<BDIM * LDIM, 128>>>(x1, conv_w, bn_g, bn_b, bn_m, bn_v,
                                     ln_m_g, ln_m_b, x2, xn);
    gemm_h<2><<<dim3(HIDD / 128, MROWS / 256), 256, GEMM_SMEM>>>(xn, w1, fc1_b, hmid, CDIM, HIDD, nullptr);
    gemm_h<3><<<dim3(CDIM / 128, MROWS / 256), 256, GEMM_SMEM>>>(hmid, w2, fc2_b, out, HIDD, CDIM, x2);
}